// round 6
// baseline (speedup 1.0000x reference)
#include <cuda_runtime.h>
#include <cuda_bf16.h>
#include <cstdint>
#include <math.h>

// ---------------------------------------------------------------- constants
#define Tn   64
#define Bn   4096
#define TDn  512
#define HDn  256
#define VDn  484
#define VDP  512
#define BM   128

// ---------------------------------------------------------------- device scratch (static, allowed)
__device__ __align__(16) __nv_bfloat16 g_W1b[Tn * HDn * TDn];   // [t][hd][td] bf16
__device__ __align__(16) __nv_bfloat16 g_W2b[Tn * VDP * HDn];   // [t][vd(pad512)][hd] bf16, pad rows zero
__device__ __align__(16) __nv_bfloat16 g_featb[Bn * TDn];       // [b][td] bf16
__device__ float g_part[Tn * 32];
__device__ float g_cnorm[Tn];

// ---------------------------------------------------------------- helpers
__device__ __forceinline__ uint32_t smem_u32(const void* p) {
    uint32_t a;
    asm("{ .reg .u64 t; cvta.to.shared.u64 t, %1; cvt.u32.u64 %0, t; }" : "=r"(a) : "l"(p));
    return a;
}

#define CP_COMMIT() asm volatile("cp.async.commit_group;" ::: "memory")
#define CP_WAIT0()  asm volatile("cp.async.wait_group 0;" ::: "memory")
#define CP_WAIT1()  asm volatile("cp.async.wait_group 1;" ::: "memory")

__device__ __forceinline__ void ldsm_x4(uint32_t* r, uint32_t addr) {
    asm volatile("ldmatrix.sync.aligned.m8n8.x4.shared.b16 {%0,%1,%2,%3}, [%4];"
        : "=r"(r[0]), "=r"(r[1]), "=r"(r[2]), "=r"(r[3]) : "r"(addr));
}
__device__ __forceinline__ void ldsm_x2(uint32_t* r, uint32_t addr) {
    asm volatile("ldmatrix.sync.aligned.m8n8.x2.shared.b16 {%0,%1}, [%2];"
        : "=r"(r[0]), "=r"(r[1]) : "r"(addr));
}
__device__ __forceinline__ void mma_bf16(float* c, const uint32_t* a, const uint32_t* b) {
    asm volatile("mma.sync.aligned.m16n8k16.row.col.f32.bf16.bf16.f32 "
        "{%0,%1,%2,%3}, {%4,%5,%6,%7}, {%8,%9}, {%0,%1,%2,%3};"
        : "+f"(c[0]), "+f"(c[1]), "+f"(c[2]), "+f"(c[3])
        : "r"(a[0]), "r"(a[1]), "r"(a[2]), "r"(a[3]), "r"(b[0]), "r"(b[1]));
}
__device__ __forceinline__ float gelu_exact(float x) {
    return 0.5f * x * (1.0f + erff(x * 0.7071067811865475f));
}

// ---------------------------------------------------------------- conversion prologue
__global__ void cvt_w1_kernel(const float* __restrict__ W1) {
    int i = blockIdx.x * blockDim.x + threadIdx.x;           // over 2097152 float4s
    float4 v = reinterpret_cast<const float4*>(W1)[i];
    reinterpret_cast<__nv_bfloat162*>(g_W1b)[i * 2]     = __floats2bfloat162_rn(v.x, v.y);
    reinterpret_cast<__nv_bfloat162*>(g_W1b)[i * 2 + 1] = __floats2bfloat162_rn(v.z, v.w);
}
__global__ void cvt_feat_kernel(const float* __restrict__ F) {
    int i = blockIdx.x * blockDim.x + threadIdx.x;           // over 524288
    float4 v = reinterpret_cast<const float4*>(F)[i];
    reinterpret_cast<__nv_bfloat162*>(g_featb)[i * 2]     = __floats2bfloat162_rn(v.x, v.y);
    reinterpret_cast<__nv_bfloat162*>(g_featb)[i * 2 + 1] = __floats2bfloat162_rn(v.z, v.w);
}
__global__ void cvt_w2_kernel(const float* __restrict__ W2) {
    int i = blockIdx.x * blockDim.x + threadIdx.x;           // over Tn*VDP*HDn/4 = 2097152
    int c4 = i & 63;                 // HDn/4
    int r  = (i >> 6) & 511;         // VDP rows
    int t  = i >> 15;
    float4 v = make_float4(0.f, 0.f, 0.f, 0.f);
    if (r < VDn) v = reinterpret_cast<const float4*>(W2)[(t * VDn + r) * 64 + c4];
    reinterpret_cast<__nv_bfloat162*>(g_W2b)[i * 2]     = __floats2bfloat162_rn(v.x, v.y);
    reinterpret_cast<__nv_bfloat162*>(g_W2b)[i * 2 + 1] = __floats2bfloat162_rn(v.z, v.w);
}
__global__ void cnorm_kernel(const float* __restrict__ cent) {
    __shared__ float red[4];
    int t = blockIdx.x;
    float s = 0.f;
    for (int c = threadIdx.x; c < VDn; c += 128) { float v = cent[t * VDn + c]; s += v * v; }
    for (int o = 16; o; o >>= 1) s += __shfl_down_sync(0xffffffffu, s, o);
    if ((threadIdx.x & 31) == 0) red[threadIdx.x >> 5] = s;
    __syncthreads();
    if (threadIdx.x == 0)
        g_cnorm[t] = fmaxf(sqrtf(red[0] + red[1] + red[2] + red[3]), 1e-8f);
}

// ---------------------------------------------------------------- SMEM layout (bytes)
#define SM_RED8   0        // 8 floats scratch
#define SM_GAMMA  1024
#define SM_BETA   2048
#define SM_B1     3072
#define SM_B2     4096     // 484 floats
#define SM_CENT   6144     // 484 floats
#define SM_H      8192     // 64KB: h bf16, 4 K-chunks of [128 rows x 128B]
#define SM_SA0    73728
#define SM_SB0    90112
#define SM_SA1    106496
#define SM_SB1    122880
#define SM_DOT    139264   // 128 x 16 floats
#define SM_NV     147456   // 128 x 16 floats
#define SMEM_TOTAL 155648

// stage a 16KB chunk [128 rows x 64 bf16] from global (uint4 granularity), swizzled
__device__ __forceinline__ void stage16k(uint32_t dst, const uint4* __restrict__ src,
                                         int stride4, int col4, int tid) {
    #pragma unroll
    for (int i = 0; i < 4; i++) {
        int idx = tid + i * 256;
        int r = idx >> 3, q = idx & 7;
        uint32_t d = dst + r * 128 + ((q * 16) ^ ((r & 7) << 4));
        const uint4* s = src + r * stride4 + col4 + q;
        asm volatile("cp.async.cg.shared.global [%0], [%1], 16;" :: "r"(d), "l"(s) : "memory");
    }
}

// one K=64 chunk of a 128x128 mma tile: 8 warps M2xN4, warp tile 64x32
__device__ __forceinline__ void compute_chunk(uint32_t bufA, uint32_t bufB,
                                              float acc[4][4][4],
                                              int warp_m, int warp_n, int lane) {
    const int lm  = lane & 15;
    const int lh  = lane >> 4;
    const int lb  = lane & 7;
    const int lbh = (lane >> 3) & 1;
    const uint32_t aRowBase = (uint32_t)(warp_m * 64 + lm);
    const uint32_t aXr = (uint32_t)((lm & 7) << 4);
    const uint32_t bXr = (uint32_t)(lb << 4);
    #pragma unroll
    for (int ks = 0; ks < 4; ks++) {
        uint32_t a[4][4];
        #pragma unroll
        for (int i = 0; i < 4; i++)
            ldsm_x4(a[i], bufA + (aRowBase + 16 * i) * 128 + (((uint32_t)(ks * 32 + lh * 16)) ^ aXr));
        uint32_t b[4][2];
        #pragma unroll
        for (int j = 0; j < 4; j++)
            ldsm_x2(b[j], bufB + (uint32_t)(warp_n * 32 + j * 8 + lb) * 128 +
                          (((uint32_t)(ks * 32 + lbh * 16)) ^ bXr));
        #pragma unroll
        for (int i = 0; i < 4; i++)
            #pragma unroll
            for (int j = 0; j < 4; j++)
                mma_bf16(acc[i][j], a[i], b[j]);
    }
}

// ---------------------------------------------------------------- main fused kernel
__global__ void __launch_bounds__(256, 1)
router_main(const float* __restrict__ gamma, const float* __restrict__ beta,
            const float* __restrict__ b1,    const float* __restrict__ b2,
            const float* __restrict__ cent) {
    extern __shared__ char smem[];
    const uint32_t sb = smem_u32(smem);
    const int tid = threadIdx.x;
    const int wid = tid >> 5;
    const int lane = tid & 31;
    const int warp_m = wid >> 2;
    const int warp_n = wid & 3;
    const int t  = blockIdx.y;
    const int bx = blockIdx.x;
    const int b0 = bx * BM;

    float* s_gamma = reinterpret_cast<float*>(smem + SM_GAMMA);
    float* s_beta  = reinterpret_cast<float*>(smem + SM_BETA);
    float* s_b1    = reinterpret_cast<float*>(smem + SM_B1);
    float* s_b2    = reinterpret_cast<float*>(smem + SM_B2);
    float* s_cent  = reinterpret_cast<float*>(smem + SM_CENT);
    for (int i = tid; i < HDn; i += 256) {
        s_gamma[i] = gamma[t * HDn + i];
        s_beta[i]  = beta[t * HDn + i];
        s_b1[i]    = b1[t * HDn + i];
    }
    for (int i = tid; i < VDn; i += 256) {
        s_b2[i]   = b2[t * VDn + i];
        s_cent[i] = cent[t * VDn + i];
    }
    __syncthreads();

    const uint4* featv = reinterpret_cast<const uint4*>(g_featb) + (size_t)b0 * 64;
    const uint4* w1v   = reinterpret_cast<const uint4*>(g_W1b);
    const uint4* w2v   = reinterpret_cast<const uint4*>(g_W2b);

    // ================= GEMM1: h[128x256] = A[128x512] . W1[t]^T, two N=128 passes
    for (int p = 0; p < 2; p++) {
        float acc[4][4][4];
        #pragma unroll
        for (int i = 0; i < 4; i++)
            #pragma unroll
            for (int j = 0; j < 4; j++)
                #pragma unroll
                for (int k = 0; k < 4; k++) acc[i][j][k] = 0.f;

        const uint4* srcB = w1v + (size_t)(t * HDn + p * 128) * 64;

        stage16k(sb + SM_SA0, featv, 64, 0, tid);
        stage16k(sb + SM_SB0, srcB,  64, 0, tid);
        CP_COMMIT();
        for (int kc = 0; kc < 8; kc++) {
            if (kc < 7) {
                uint32_t sa = ((kc + 1) & 1) ? SM_SA1 : SM_SA0;
                uint32_t sbuf = ((kc + 1) & 1) ? SM_SB1 : SM_SB0;
                stage16k(sb + sa,   featv, 64, (kc + 1) * 8, tid);
                stage16k(sb + sbuf, srcB,  64, (kc + 1) * 8, tid);
                CP_COMMIT();
                CP_WAIT1();
            } else {
                CP_WAIT0();
            }
            __syncthreads();
            compute_chunk(sb + ((kc & 1) ? SM_SA1 : SM_SA0),
                          sb + ((kc & 1) ? SM_SB1 : SM_SB0),
                          acc, warp_m, warp_n, lane);
            __syncthreads();
        }

        // store h (+b1) as bf16 into swizzled s_h chunks
        #pragma unroll
        for (int i = 0; i < 4; i++) {
            int row0 = warp_m * 64 + i * 16 + (lane >> 2);
            #pragma unroll
            for (int rr = 0; rr < 2; rr++) {
                int row = row0 + rr * 8;
                uint32_t xr = (uint32_t)((row & 7) << 4);
                #pragma unroll
                for (int j = 0; j < 4; j++) {
                    int col = p * 128 + warp_n * 32 + j * 8 + (lane & 3) * 2;
                    float v0 = acc[i][j][rr * 2 + 0] + s_b1[col];
                    float v1 = acc[i][j][rr * 2 + 1] + s_b1[col + 1];
                    __nv_bfloat162 pk = __floats2bfloat162_rn(v0, v1);
                    uint32_t addr = sb + SM_H + (uint32_t)(col >> 6) * 16384 +
                                    (uint32_t)row * 128 + ((uint32_t)((col & 63) * 2) ^ xr);
                    asm volatile("st.shared.b32 [%0], %1;" :: "r"(addr), "r"(*(uint32_t*)&pk) : "memory");
                }
            }
        }
    }
    __syncthreads();

    // ================= LayerNorm + exact GELU, in place on s_h
    {
        const int row = tid >> 1, hf = tid & 1;
        const uint32_t xr = (uint32_t)((row & 7) << 4);
        uint32_t hv[64];
        float sum = 0.f, sq = 0.f;
        #pragma unroll
        for (int ch = 0; ch < 2; ch++) {
            uint32_t cb = sb + SM_H + (uint32_t)(2 * hf + ch) * 16384 + (uint32_t)row * 128;
            #pragma unroll
            for (int q = 0; q < 32; q++) {
                uint32_t v;
                asm volatile("ld.shared.b32 %0, [%1];" : "=r"(v) : "r"(cb + (((uint32_t)(q * 4)) ^ xr)));
                hv[ch * 32 + q] = v;
                float2 f = __bfloat1622float2(*reinterpret_cast<__nv_bfloat162*>(&v));
                sum += f.x + f.y; sq += f.x * f.x + f.y * f.y;
            }
        }
        sum += __shfl_xor_sync(0xffffffffu, sum, 1);
        sq  += __shfl_xor_sync(0xffffffffu, sq, 1);
        const float mu = sum * (1.0f / HDn);
        const float var = sq * (1.0f / HDn) - mu * mu;
        const float rs = rsqrtf(var + 1e-5f);
        #pragma unroll
        for (int ch = 0; ch < 2; ch++) {
            uint32_t cb = sb + SM_H + (uint32_t)(2 * hf + ch) * 16384 + (uint32_t)row * 128;
            #pragma unroll
            for (int q = 0; q < 32; q++) {
                int col = hf * 128 + ch * 64 + q * 2;
                uint32_t v = hv[ch * 32 + q];
                float2 f = __bfloat1622float2(*reinterpret_cast<__nv_bfloat162*>(&v));
                float x0 = (f.x - mu) * rs * s_gamma[col]     + s_beta[col];
                float x1 = (f.y - mu) * rs * s_gamma[col + 1] + s_beta[col + 1];
                __nv_bfloat162 pk = __floats2bfloat162_rn(gelu_exact(x0), gelu_exact(x1));
                asm volatile("st.shared.b32 [%0], %1;"
                    :: "r"(cb + (((uint32_t)(q * 4)) ^ xr)), "r"(*(uint32_t*)&pk) : "memory");
            }
        }
    }
    __syncthreads();

    // ================= GEMM2: v[128x512pad] = h[128x256] . W2[t]^T, 4 N=128 passes
    float dotp[8], nvp[8];
    #pragma unroll
    for (int k = 0; k < 8; k++) { dotp[k] = 0.f; nvp[k] = 0.f; }

    for (int p = 0; p < 4; p++) {
        float acc[4][4][4];
        #pragma unroll
        for (int i = 0; i < 4; i++)
            #pragma unroll
            for (int j = 0; j < 4; j++)
                #pragma unroll
                for (int k = 0; k < 4; k++) acc[i][j][k] = 0.f;

        const uint4* srcB = w2v + (size_t)(t * VDP + p * 128) * 32;

        stage16k(sb + SM_SB0, srcB, 32, 0, tid);
        CP_COMMIT();
        for (int kc = 0; kc < 4; kc++) {
            if (kc < 3) {
                stage16k(sb + (((kc + 1) & 1) ? SM_SB1 : SM_SB0), srcB, 32, (kc + 1) * 8, tid);
                CP_COMMIT();
                CP_WAIT1();
            } else {
                CP_WAIT0();
            }
            __syncthreads();
            compute_chunk(sb + SM_H + (uint32_t)kc * 16384,
                          sb + ((kc & 1) ? SM_SB1 : SM_SB0),
                          acc, warp_m, warp_n, lane);
            __syncthreads();
        }

        // cosine partials (register-resident, deterministic per-thread ownership)
        #pragma unroll
        for (int i = 0; i < 4; i++) {
            #pragma unroll
            for (int rr = 0; rr < 2; rr++) {
                int lr = i * 2 + rr;
                #pragma unroll
                for (int j = 0; j < 4; j++) {
                    int col = p * 128 + warp_n * 32 + j * 8 + (lane & 3) * 2;
                    #pragma unroll
                    for (int cc = 0; cc < 2; cc++) {
                        int c = col + cc;
                        if (c < VDn) {
                            float v = acc[i][j][rr * 2 + cc] + s_b2[c];
                            dotp[lr] += v * s_cent[c];
                            nvp[lr]  += v * v;
                        }
                    }
                }
            }
        }
    }

    // ================= deterministic reduction
    {
        float* s_dot = reinterpret_cast<float*>(smem + SM_DOT);
        float* s_nv  = reinterpret_cast<float*>(smem + SM_NV);
        int slot = warp_n * 4 + (lane & 3);
        #pragma unroll
        for (int i = 0; i < 4; i++)
            #pragma unroll
            for (int rr = 0; rr < 2; rr++) {
                int row = warp_m * 64 + i * 16 + (lane >> 2) + rr * 8;
                s_dot[row * 16 + slot] = dotp[i * 2 + rr];
                s_nv [row * 16 + slot] = nvp [i * 2 + rr];
            }
        __syncthreads();
        float contrib = 0.f;
        if (tid < 128) {
            float dt = 0.f, nv = 0.f;
            #pragma unroll
            for (int s = 0; s < 16; s++) { dt += s_dot[tid * 16 + s]; nv += s_nv[tid * 16 + s]; }
            float vn = fmaxf(sqrtf(nv), 1e-8f);
            contrib = 1.0f - dt / (vn * g_cnorm[t]);
        }
        for (int o = 16; o; o >>= 1) contrib += __shfl_down_sync(0xffffffffu, contrib, o);
        float* red8 = reinterpret_cast<float*>(smem + SM_RED8);
        if (lane == 0) red8[wid] = contrib;
        __syncthreads();
        if (tid == 0)
            g_part[t * 32 + bx] = red8[0] + red8[1] + red8[2] + red8[3];  // warps 4-7 hold 0
    }
}

// ---------------------------------------------------------------- finalize: mean + argmin
__global__ void finalize_kernel(float* __restrict__ out, int out_size) {
    __shared__ float d[Tn];
    int t = threadIdx.x;
    if (t < Tn) {
        float s = 0.f;
        for (int b = 0; b < 32; b++) s += g_part[t * 32 + b];   // fixed order: deterministic
        float dist = s * (1.0f / Bn);
        d[t] = dist;
        if (out_size >= Tn) out[t] = dist;
    }
    __syncthreads();
    if (t == 0) {
        int best = 0; float bv = d[0];
        for (int i = 1; i < Tn; i++) if (d[i] < bv) { bv = d[i]; best = i; }
        if (out_size > Tn)       out[Tn] = (float)best;
        else if (out_size == 1)  reinterpret_cast<int*>(out)[0] = best;
    }
}

// ---------------------------------------------------------------- launch
extern "C" void kernel_launch(void* const* d_in, const int* in_sizes, int n_in,
                              void* d_out, int out_size) {
    const float* t_feat = (const float*)d_in[0];
    const float* W1     = (const float*)d_in[1];
    const float* b1     = (const float*)d_in[2];
    const float* gamma  = (const float*)d_in[3];
    const float* beta   = (const float*)d_in[4];
    const float* W2     = (const float*)d_in[5];
    const float* b2     = (const float*)d_in[6];
    const float* cent   = (const float*)d_in[7];

    cudaFuncSetAttribute(router_main, cudaFuncAttributeMaxDynamicSharedMemorySize, SMEM_TOTAL);

    cvt_w1_kernel  <<<2097152 / 256, 256>>>(W1);
    cvt_feat_kernel<<< 524288 / 256, 256>>>(t_feat);
    cvt_w2_kernel  <<<2097152 / 256, 256>>>(W2);
    cnorm_kernel   <<<Tn, 128>>>(cent);

    dim3 grid(32, Tn);
    router_main<<<grid, 256, SMEM_TOTAL>>>(gamma, beta, b1, b2, cent);

    finalize_kernel<<<1, Tn>>>((float*)d_out, out_size);
}

// round 11
// speedup vs baseline: 1.0797x; 1.0797x over previous
#include <cuda_runtime.h>
#include <cuda_bf16.h>
#include <cstdint>
#include <math.h>

// ---------------------------------------------------------------- constants
#define Tn   64
#define Bn   4096
#define TDn  512
#define HDn  256
#define VDn  484
#define VDP  512
#define BM   128

// ---------------------------------------------------------------- device scratch (static, allowed)
__device__ __align__(16) __nv_bfloat16 g_W1b[Tn * HDn * TDn];   // [t][hd][td] bf16
__device__ __align__(16) __nv_bfloat16 g_W2b[Tn * VDP * HDn];   // [t][vd(pad512)][hd] bf16, pad rows zero
__device__ __align__(16) __nv_bfloat16 g_featb[Bn * TDn];       // [b][td] bf16
__device__ float g_part[Tn * 32];
__device__ float g_cnorm[Tn];

// ---------------------------------------------------------------- helpers
__device__ __forceinline__ uint32_t smem_u32(const void* p) {
    uint32_t a;
    asm("{ .reg .u64 t; cvta.to.shared.u64 t, %1; cvt.u32.u64 %0, t; }" : "=r"(a) : "l"(p));
    return a;
}

#define CP_COMMIT() asm volatile("cp.async.commit_group;" ::: "memory")
#define CP_WAIT0()  asm volatile("cp.async.wait_group 0;" ::: "memory")
#define CP_WAIT1()  asm volatile("cp.async.wait_group 1;" ::: "memory")

__device__ __forceinline__ void ldsm_x4(uint32_t* r, uint32_t addr) {
    asm volatile("ldmatrix.sync.aligned.m8n8.x4.shared.b16 {%0,%1,%2,%3}, [%4];"
        : "=r"(r[0]), "=r"(r[1]), "=r"(r[2]), "=r"(r[3]) : "r"(addr));
}
__device__ __forceinline__ void mma_bf16(float* c, const uint32_t* a, const uint32_t* b) {
    asm volatile("mma.sync.aligned.m16n8k16.row.col.f32.bf16.bf16.f32 "
        "{%0,%1,%2,%3}, {%4,%5,%6,%7}, {%8,%9}, {%0,%1,%2,%3};"
        : "+f"(c[0]), "+f"(c[1]), "+f"(c[2]), "+f"(c[3])
        : "r"(a[0]), "r"(a[1]), "r"(a[2]), "r"(a[3]), "r"(b[0]), "r"(b[1]));
}
__device__ __forceinline__ float gelu_exact(float x) {
    return 0.5f * x * (1.0f + erff(x * 0.7071067811865475f));
}

// ---------------------------------------------------------------- conversion prologue
__global__ void cvt_w1_kernel(const float* __restrict__ W1) {
    int i = blockIdx.x * blockDim.x + threadIdx.x;           // over 2097152 float4s
    float4 v = reinterpret_cast<const float4*>(W1)[i];
    reinterpret_cast<__nv_bfloat162*>(g_W1b)[i * 2]     = __floats2bfloat162_rn(v.x, v.y);
    reinterpret_cast<__nv_bfloat162*>(g_W1b)[i * 2 + 1] = __floats2bfloat162_rn(v.z, v.w);
}
__global__ void cvt_feat_kernel(const float* __restrict__ F) {
    int i = blockIdx.x * blockDim.x + threadIdx.x;           // over 524288
    float4 v = reinterpret_cast<const float4*>(F)[i];
    reinterpret_cast<__nv_bfloat162*>(g_featb)[i * 2]     = __floats2bfloat162_rn(v.x, v.y);
    reinterpret_cast<__nv_bfloat162*>(g_featb)[i * 2 + 1] = __floats2bfloat162_rn(v.z, v.w);
}
__global__ void cvt_w2_kernel(const float* __restrict__ W2) {
    int i = blockIdx.x * blockDim.x + threadIdx.x;           // over Tn*VDP*HDn/4 = 2097152
    int c4 = i & 63;                 // HDn/4
    int r  = (i >> 6) & 511;         // VDP rows
    int t  = i >> 15;
    float4 v = make_float4(0.f, 0.f, 0.f, 0.f);
    if (r < VDn) v = reinterpret_cast<const float4*>(W2)[(t * VDn + r) * 64 + c4];
    reinterpret_cast<__nv_bfloat162*>(g_W2b)[i * 2]     = __floats2bfloat162_rn(v.x, v.y);
    reinterpret_cast<__nv_bfloat162*>(g_W2b)[i * 2 + 1] = __floats2bfloat162_rn(v.z, v.w);
}
__global__ void cnorm_kernel(const float* __restrict__ cent) {
    __shared__ float red[4];
    int t = blockIdx.x;
    float s = 0.f;
    for (int c = threadIdx.x; c < VDn; c += 128) { float v = cent[t * VDn + c]; s += v * v; }
    for (int o = 16; o; o >>= 1) s += __shfl_down_sync(0xffffffffu, s, o);
    if ((threadIdx.x & 31) == 0) red[threadIdx.x >> 5] = s;
    __syncthreads();
    if (threadIdx.x == 0)
        g_cnorm[t] = fmaxf(sqrtf(red[0] + red[1] + red[2] + red[3]), 1e-8f);
}

// ---------------------------------------------------------------- SMEM layout (bytes)
#define SM_RED8   0        // 8 floats scratch
#define SM_GAMMA  1024
#define SM_BETA   2048
#define SM_B1     3072
#define SM_B2     4096     // 484 floats
#define SM_CENT   6144     // 484 floats
#define SM_H      8192     // 64KB: h bf16, 4 K-chunks of [128 rows x 128B]
#define SM_SA0    73728    // 16KB
#define SM_SA1    90112    // 16KB
#define SM_SB0    106496   // 32KB
#define SM_SB1    139264   // 32KB
#define SMEM_TOTAL 172032
// reduction scratch overlays SA0 (dead after GEMM1)
#define SM_DOT    SM_SA0           // 128 x 16 floats = 8KB
#define SM_NV     (SM_SA0 + 8192)  // 8KB

// stage NITER*32 rows x 64 bf16 (128B/row) from global, swizzled
template<int NITER>
__device__ __forceinline__ void stage_rows(uint32_t dst, const uint4* __restrict__ src,
                                           int stride4, int col4, int tid) {
    #pragma unroll
    for (int i = 0; i < NITER; i++) {
        int idx = tid + i * 256;
        int r = idx >> 3, q = idx & 7;
        uint32_t d = dst + r * 128 + ((q * 16) ^ ((r & 7) << 4));
        const uint4* s = src + r * stride4 + col4 + q;
        asm volatile("cp.async.cg.shared.global [%0], [%1], 16;" :: "r"(d), "l"(s) : "memory");
    }
}

// one K=64 chunk of a 128x256 mma tile: 8 warps M2xN4, warp tile 64x64
__device__ __forceinline__ void compute_chunk(uint32_t bufA, uint32_t bufB,
                                              float acc[4][8][4],
                                              int warp_m, int warp_n, int lane) {
    const int lm = lane & 15;
    const int lh = lane >> 4;
    const uint32_t aRowBase = (uint32_t)(warp_m * 64 + lm);
    const uint32_t aXr = (uint32_t)((lm & 7) << 4);
    // B lane mapping for ldsm_x4 over 16 rows x k16:
    // groups g=lane>>3: g0 rows+0..7 kLo | g1 rows+0..7 kHi | g2 rows+8..15 kLo | g3 kHi
    const int brow16 = ((lane >> 4) << 3) + (lane & 7);       // 0..15
    const int bkh    = (lane >> 3) & 1;
    #pragma unroll
    for (int ks = 0; ks < 4; ks++) {
        uint32_t a[4][4];
        #pragma unroll
        for (int i = 0; i < 4; i++)
            ldsm_x4(a[i], bufA + (aRowBase + 16 * i) * 128 + (((uint32_t)(ks * 32 + lh * 16)) ^ aXr));
        uint32_t b[4][4];
        #pragma unroll
        for (int j2 = 0; j2 < 4; j2++) {
            uint32_t row = (uint32_t)(warp_n * 64 + j2 * 16 + brow16);
            ldsm_x4(b[j2], bufB + row * 128 +
                    (((uint32_t)(ks * 32 + bkh * 16)) ^ ((row & 7) << 4)));
        }
        #pragma unroll
        for (int i = 0; i < 4; i++)
            #pragma unroll
            for (int j2 = 0; j2 < 4; j2++) {
                mma_bf16(acc[i][j2 * 2],     a[i], &b[j2][0]);
                mma_bf16(acc[i][j2 * 2 + 1], a[i], &b[j2][2]);
            }
    }
}

// ---------------------------------------------------------------- main fused kernel
__global__ void __launch_bounds__(256, 1)
router_main(const float* __restrict__ gamma, const float* __restrict__ beta,
            const float* __restrict__ b1,    const float* __restrict__ b2,
            const float* __restrict__ cent) {
    extern __shared__ char smem[];
    const uint32_t sb = smem_u32(smem);
    const int tid = threadIdx.x;
    const int wid = tid >> 5;
    const int lane = tid & 31;
    const int warp_m = wid >> 2;
    const int warp_n = wid & 3;
    const int t  = blockIdx.y;
    const int bx = blockIdx.x;
    const int b0 = bx * BM;

    const uint4* featv = reinterpret_cast<const uint4*>(g_featb) + (size_t)b0 * 64;
    const uint4* w1v   = reinterpret_cast<const uint4*>(g_W1b) + (size_t)t * HDn * 64;
    const uint4* w2v   = reinterpret_cast<const uint4*>(g_W2b) + (size_t)t * VDP * 32;

    // kick off GEMM1 chunk 0 ASAP (overlaps bias loads)
    stage_rows<4>(sb + SM_SA0, featv, 64, 0, tid);
    stage_rows<8>(sb + SM_SB0, w1v,   64, 0, tid);
    CP_COMMIT();

    float* s_gamma = reinterpret_cast<float*>(smem + SM_GAMMA);
    float* s_beta  = reinterpret_cast<float*>(smem + SM_BETA);
    float* s_b1    = reinterpret_cast<float*>(smem + SM_B1);
    float* s_b2    = reinterpret_cast<float*>(smem + SM_B2);
    float* s_cent  = reinterpret_cast<float*>(smem + SM_CENT);
    for (int i = tid; i < HDn; i += 256) {
        s_gamma[i] = gamma[t * HDn + i];
        s_beta[i]  = beta[t * HDn + i];
        s_b1[i]    = b1[t * HDn + i];
    }
    for (int i = tid; i < VDn; i += 256) {
        s_b2[i]   = b2[t * VDn + i];
        s_cent[i] = cent[t * VDn + i];
    }

    float acc[4][8][4];
    #pragma unroll
    for (int i = 0; i < 4; i++)
        #pragma unroll
        for (int j = 0; j < 8; j++)
            #pragma unroll
            for (int k = 0; k < 4; k++) acc[i][j][k] = 0.f;

    // ================= GEMM1: h[128x256] = A[128x512] . W1[t]^T, K in 8 chunks of 64
    for (int kc = 0; kc < 8; kc++) {
        const uint32_t nb = ((kc + 1) & 1) ? 1u : 0u;
        if (kc < 7) {
            stage_rows<4>(sb + (nb ? SM_SA1 : SM_SA0), featv, 64, (kc + 1) * 8, tid);
            stage_rows<8>(sb + (nb ? SM_SB1 : SM_SB0), w1v,   64, (kc + 1) * 8, tid);
        } else {
            // prefetch GEMM2 chunk 0 (W2 pass 0, K chunk 0) into SB0
            stage_rows<8>(sb + SM_SB0, w2v, 32, 0, tid);
        }
        CP_COMMIT();
        CP_WAIT1();
        __syncthreads();
        compute_chunk(sb + ((kc & 1) ? SM_SA1 : SM_SA0),
                      sb + ((kc & 1) ? SM_SB1 : SM_SB0),
                      acc, warp_m, warp_n, lane);
        __syncthreads();
    }

    // store h (+b1) as bf16 into swizzled s_h chunks
    #pragma unroll
    for (int i = 0; i < 4; i++) {
        int row0 = warp_m * 64 + i * 16 + (lane >> 2);
        #pragma unroll
        for (int rr = 0; rr < 2; rr++) {
            int row = row0 + rr * 8;
            uint32_t xr = (uint32_t)((row & 7) << 4);
            #pragma unroll
            for (int j = 0; j < 8; j++) {
                int col = warp_n * 64 + j * 8 + (lane & 3) * 2;
                float v0 = acc[i][j][rr * 2 + 0] + s_b1[col];
                float v1 = acc[i][j][rr * 2 + 1] + s_b1[col + 1];
                __nv_bfloat162 pk = __floats2bfloat162_rn(v0, v1);
                uint32_t addr = sb + SM_H + (uint32_t)(col >> 6) * 16384 +
                                (uint32_t)row * 128 + ((uint32_t)((col & 63) * 2) ^ xr);
                asm volatile("st.shared.b32 [%0], %1;" :: "r"(addr), "r"(*(uint32_t*)&pk) : "memory");
            }
        }
    }
    __syncthreads();

    // ================= LayerNorm + exact GELU, in place on s_h
    {
        const int row = tid >> 1, hf = tid & 1;
        const uint32_t xr = (uint32_t)((row & 7) << 4);
        uint32_t hv[64];
        float sum = 0.f, sq = 0.f;
        #pragma unroll
        for (int ch = 0; ch < 2; ch++) {
            uint32_t cb = sb + SM_H + (uint32_t)(2 * hf + ch) * 16384 + (uint32_t)row * 128;
            #pragma unroll
            for (int q = 0; q < 32; q++) {
                uint32_t v;
                asm volatile("ld.shared.b32 %0, [%1];" : "=r"(v) : "r"(cb + (((uint32_t)(q * 4)) ^ xr)));
                hv[ch * 32 + q] = v;
                float2 f = __bfloat1622float2(*reinterpret_cast<__nv_bfloat162*>(&v));
                sum += f.x + f.y; sq += f.x * f.x + f.y * f.y;
            }
        }
        sum += __shfl_xor_sync(0xffffffffu, sum, 1);
        sq  += __shfl_xor_sync(0xffffffffu, sq, 1);
        const float mu = sum * (1.0f / HDn);
        const float var = sq * (1.0f / HDn) - mu * mu;
        const float rs = rsqrtf(var + 1e-5f);
        #pragma unroll
        for (int ch = 0; ch < 2; ch++) {
            uint32_t cb = sb + SM_H + (uint32_t)(2 * hf + ch) * 16384 + (uint32_t)row * 128;
            #pragma unroll
            for (int q = 0; q < 32; q++) {
                int col = hf * 128 + ch * 64 + q * 2;
                uint32_t v = hv[ch * 32 + q];
                float2 f = __bfloat1622float2(*reinterpret_cast<__nv_bfloat162*>(&v));
                float x0 = (f.x - mu) * rs * s_gamma[col]     + s_beta[col];
                float x1 = (f.y - mu) * rs * s_gamma[col + 1] + s_beta[col + 1];
                __nv_bfloat162 pk = __floats2bfloat162_rn(gelu_exact(x0), gelu_exact(x1));
                asm volatile("st.shared.b32 [%0], %1;"
                    :: "r"(cb + (((uint32_t)(q * 4)) ^ xr)), "r"(*(uint32_t*)&pk) : "memory");
            }
        }
    }
    __syncthreads();

    // ================= GEMM2: v[128x512pad] = h[128x256] . W2[t]^T
    // 8 continuous chunks: pass = c>>2 (N 256 halves), kc = c&3 (K chunks of 64)
    float dotp[8], nvp[8];
    #pragma unroll
    for (int k = 0; k < 8; k++) { dotp[k] = 0.f; nvp[k] = 0.f; }
    #pragma unroll
    for (int i = 0; i < 4; i++)
        #pragma unroll
        for (int j = 0; j < 8; j++)
            #pragma unroll
            for (int k = 0; k < 4; k++) acc[i][j][k] = 0.f;

    for (int c = 0; c < 8; c++) {
        if (c < 7) {
            int cn = c + 1;
            stage_rows<8>(sb + ((cn & 1) ? SM_SB1 : SM_SB0),
                          w2v + (size_t)((cn >> 2) * 256) * 32, 32, (cn & 3) * 8, tid);
            CP_COMMIT();
            CP_WAIT1();
        } else {
            CP_WAIT0();
        }
        __syncthreads();
        compute_chunk(sb + SM_H + (uint32_t)(c & 3) * 16384,
                      sb + ((c & 1) ? SM_SB1 : SM_SB0),
                      acc, warp_m, warp_n, lane);
        __syncthreads();

        if ((c & 3) == 3) {
            const int p = c >> 2;
            // cosine partials (register-resident, deterministic per-thread ownership)
            #pragma unroll
            for (int i = 0; i < 4; i++) {
                #pragma unroll
                for (int rr = 0; rr < 2; rr++) {
                    int lr = i * 2 + rr;
                    #pragma unroll
                    for (int j = 0; j < 8; j++) {
                        int col = p * 256 + warp_n * 64 + j * 8 + (lane & 3) * 2;
                        #pragma unroll
                        for (int cc = 0; cc < 2; cc++) {
                            int cidx = col + cc;
                            if (cidx < VDn) {
                                float v = acc[i][j][rr * 2 + cc] + s_b2[cidx];
                                dotp[lr] += v * s_cent[cidx];
                                nvp[lr]  += v * v;
                            }
                            acc[i][j][rr * 2 + cc] = 0.f;   // reset for next pass
                        }
                    }
                }
            }
        }
    }

    // ================= deterministic reduction
    {
        float* s_dot = reinterpret_cast<float*>(smem + SM_DOT);
        float* s_nv  = reinterpret_cast<float*>(smem + SM_NV);
        int slot = warp_n * 4 + (lane & 3);
        #pragma unroll
        for (int i = 0; i < 4; i++)
            #pragma unroll
            for (int rr = 0; rr < 2; rr++) {
                int row = warp_m * 64 + i * 16 + (lane >> 2) + rr * 8;
                s_dot[row * 16 + slot] = dotp[i * 2 + rr];
                s_nv [row * 16 + slot] = nvp [i * 2 + rr];
            }
        __syncthreads();
        float contrib = 0.f;
        if (tid < 128) {
            float dt = 0.f, nv = 0.f;
            #pragma unroll
            for (int s = 0; s < 16; s++) { dt += s_dot[tid * 16 + s]; nv += s_nv[tid * 16 + s]; }
            float vn = fmaxf(sqrtf(nv), 1e-8f);
            contrib = 1.0f - dt / (vn * g_cnorm[t]);
        }
        for (int o = 16; o; o >>= 1) contrib += __shfl_down_sync(0xffffffffu, contrib, o);
        float* red8 = reinterpret_cast<float*>(smem + SM_RED8);
        if (lane == 0) red8[wid] = contrib;
        __syncthreads();
        if (tid == 0)
            g_part[t * 32 + bx] = red8[0] + red8[1] + red8[2] + red8[3];  // warps 4-7 hold 0
    }
}

// ---------------------------------------------------------------- finalize: mean + argmin
__global__ void finalize_kernel(float* __restrict__ out, int out_size) {
    __shared__ float d[Tn];
    int t = threadIdx.x;
    if (t < Tn) {
        float s = 0.f;
        for (int b = 0; b < 32; b++) s += g_part[t * 32 + b];   // fixed order: deterministic
        float dist = s * (1.0f / Bn);
        d[t] = dist;
        if (out_size >= Tn) out[t] = dist;
    }
    __syncthreads();
    if (t == 0) {
        int best = 0; float bv = d[0];
        for (int i = 1; i < Tn; i++) if (d[i] < bv) { bv = d[i]; best = i; }
        if (out_size > Tn)       out[Tn] = (float)best;
        else if (out_size == 1)  reinterpret_cast<int*>(out)[0] = best;
    }
}

// ---------------------------------------------------------------- launch
extern "C" void kernel_launch(void* const* d_in, const int* in_sizes, int n_in,
                              void* d_out, int out_size) {
    const float* t_feat = (const float*)d_in[0];
    const float* W1     = (const float*)d_in[1];
    const float* b1     = (const float*)d_in[2];
    const float* gamma  = (const float*)d_in[3];
    const float* beta   = (const float*)d_in[4];
    const float* W2     = (const float*)d_in[5];
    const float* b2     = (const float*)d_in[6];
    const float* cent   = (const float*)d_in[7];

    cudaFuncSetAttribute(router_main, cudaFuncAttributeMaxDynamicSharedMemorySize, SMEM_TOTAL);

    cvt_w1_kernel  <<<2097152 / 256, 256>>>(W1);
    cvt_feat_kernel<<< 524288 / 256, 256>>>(t_feat);
    cvt_w2_kernel  <<<2097152 / 256, 256>>>(W2);
    cnorm_kernel   <<<Tn, 128>>>(cent);

    dim3 grid(32, Tn);
    router_main<<<grid, 256, SMEM_TOTAL>>>(gamma, beta, b1, b2, cent);

    finalize_kernel<<<1, Tn>>>((float*)d_out, out_size);
}

// round 15
// speedup vs baseline: 1.1160x; 1.0336x over previous
#include <cuda_runtime.h>
#include <cuda_bf16.h>
#include <cstdint>
#include <math.h>

// ---------------------------------------------------------------- constants
#define Tn   64
#define Bn   4096
#define TDn  512
#define HDn  256
#define VDn  484
#define VDP  512
#define BM   128

// ---------------------------------------------------------------- device scratch (static, allowed)
__device__ __align__(16) __nv_bfloat16 g_W1b[Tn * HDn * TDn];   // [t][hd][td] bf16
__device__ __align__(16) __nv_bfloat16 g_W2b[Tn * VDP * HDn];   // [t][vd(pad512)][hd] bf16, pad rows zero
__device__ __align__(16) __nv_bfloat16 g_featb[Bn * TDn];       // [b][td] bf16
__device__ float g_part[Tn * 32];
__device__ float g_cnorm[Tn];

// ---------------------------------------------------------------- helpers
__device__ __forceinline__ uint32_t smem_u32(const void* p) {
    uint32_t a;
    asm("{ .reg .u64 t; cvta.to.shared.u64 t, %1; cvt.u32.u64 %0, t; }" : "=r"(a) : "l"(p));
    return a;
}

#define CP_COMMIT() asm volatile("cp.async.commit_group;" ::: "memory")
#define CP_WAIT0()  asm volatile("cp.async.wait_group 0;" ::: "memory")

__device__ __forceinline__ void ldsm_x4(uint32_t* r, uint32_t addr) {
    asm volatile("ldmatrix.sync.aligned.m8n8.x4.shared.b16 {%0,%1,%2,%3}, [%4];"
        : "=r"(r[0]), "=r"(r[1]), "=r"(r[2]), "=r"(r[3]) : "r"(addr));
}
__device__ __forceinline__ void mma_bf16(float* c, const uint32_t* a, const uint32_t* b) {
    asm volatile("mma.sync.aligned.m16n8k16.row.col.f32.bf16.bf16.f32 "
        "{%0,%1,%2,%3}, {%4,%5,%6,%7}, {%8,%9}, {%0,%1,%2,%3};"
        : "+f"(c[0]), "+f"(c[1]), "+f"(c[2]), "+f"(c[3])
        : "r"(a[0]), "r"(a[1]), "r"(a[2]), "r"(a[3]), "r"(b[0]), "r"(b[1]));
}
__device__ __forceinline__ float gelu_exact(float x) {
    return 0.5f * x * (1.0f + erff(x * 0.7071067811865475f));
}

// ---------------------------------------------------------------- fused conversion prologue
// blocks [0,8192): W1 -> bf16          (2097152 float4s)
// blocks [8192,10240): feat -> bf16    (524288 float4s)
// blocks [10240,18432): W2 -> bf16 pad (2097152 bf16x4 outputs)
// blocks [18432,18496): centroid norms (one task per block)
#define PREP_BLOCKS 18496
__global__ void prep_kernel(const float* __restrict__ W1, const float* __restrict__ F,
                            const float* __restrict__ W2, const float* __restrict__ cent) {
    const int blk = blockIdx.x;
    const int tid = threadIdx.x;
    if (blk < 8192) {
        int i = blk * 256 + tid;
        float4 v = reinterpret_cast<const float4*>(W1)[i];
        reinterpret_cast<__nv_bfloat162*>(g_W1b)[i * 2]     = __floats2bfloat162_rn(v.x, v.y);
        reinterpret_cast<__nv_bfloat162*>(g_W1b)[i * 2 + 1] = __floats2bfloat162_rn(v.z, v.w);
    } else if (blk < 10240) {
        int i = (blk - 8192) * 256 + tid;
        float4 v = reinterpret_cast<const float4*>(F)[i];
        reinterpret_cast<__nv_bfloat162*>(g_featb)[i * 2]     = __floats2bfloat162_rn(v.x, v.y);
        reinterpret_cast<__nv_bfloat162*>(g_featb)[i * 2 + 1] = __floats2bfloat162_rn(v.z, v.w);
    } else if (blk < 18432) {
        int i = (blk - 10240) * 256 + tid;
        int c4 = i & 63;                 // HDn/4
        int r  = (i >> 6) & 511;         // VDP rows
        int t  = i >> 15;
        float4 v = make_float4(0.f, 0.f, 0.f, 0.f);
        if (r < VDn) v = reinterpret_cast<const float4*>(W2)[(t * VDn + r) * 64 + c4];
        reinterpret_cast<__nv_bfloat162*>(g_W2b)[i * 2]     = __floats2bfloat162_rn(v.x, v.y);
        reinterpret_cast<__nv_bfloat162*>(g_W2b)[i * 2 + 1] = __floats2bfloat162_rn(v.z, v.w);
    } else {
        __shared__ float red[8];
        int t = blk - 18432;
        float s = 0.f;
        for (int c = tid; c < VDn; c += 256) { float v = cent[t * VDn + c]; s += v * v; }
        for (int o = 16; o; o >>= 1) s += __shfl_down_sync(0xffffffffu, s, o);
        if ((tid & 31) == 0) red[tid >> 5] = s;
        __syncthreads();
        if (tid == 0) {
            float a = 0.f;
            #pragma unroll
            for (int w = 0; w < 8; w++) a += red[w];
            g_cnorm[t] = fmaxf(sqrtf(a), 1e-8f);
        }
    }
}

// ---------------------------------------------------------------- SMEM layout (bytes)
#define SM_RED8   0        // 8 floats scratch
#define SM_GAMMA  1024
#define SM_BETA   2048
#define SM_B1     3072
#define SM_B2     4096     // 484 floats
#define SM_CENT   6144     // 484 floats
#define SM_H      8192     // 64KB: h bf16, 4 K-chunks of [128 rows x 128B]
#define SM_SA0    73728    // 16KB
#define SM_SA1    90112    // 16KB
#define SM_SB0    106496   // 32KB
#define SM_SB1    139264   // 32KB
#define SMEM_TOTAL 172032
// reduction scratch overlays SA0 (dead after GEMM1)
#define SM_DOT    SM_SA0           // 128 x 16 floats = 8KB
#define SM_NV     (SM_SA0 + 8192)  // 8KB

// stage NITER*32 rows x 64 bf16 (128B/row) from global, swizzled
template<int NITER>
__device__ __forceinline__ void stage_rows(uint32_t dst, const uint4* __restrict__ src,
                                           int stride4, int col4, int tid) {
    #pragma unroll
    for (int i = 0; i < NITER; i++) {
        int idx = tid + i * 256;
        int r = idx >> 3, q = idx & 7;
        uint32_t d = dst + r * 128 + ((q * 16) ^ ((r & 7) << 4));
        const uint4* s = src + r * stride4 + col4 + q;
        asm volatile("cp.async.cg.shared.global [%0], [%1], 16;" :: "r"(d), "l"(s) : "memory");
    }
}

// one K=64 chunk of a 128x256 mma tile: 8 warps M2xN4, warp tile 64x64.
// B fragments double-buffered across ks slices to hide LDSM latency.
__device__ __forceinline__ void compute_chunk(uint32_t bufA, uint32_t bufB,
                                              float acc[4][8][4],
                                              int warp_m, int warp_n, int lane) {
    const int lm = lane & 15;
    const int lh = lane >> 4;
    const uint32_t aRowBase = (uint32_t)(warp_m * 64 + lm);
    const uint32_t aXr = (uint32_t)((lm & 7) << 4);
    // B lane mapping for ldsm_x4 over 16 rows x k16
    const int brow16 = ((lane >> 4) << 3) + (lane & 7);       // 0..15
    const int bkh    = (lane >> 3) & 1;

    uint32_t b[2][4][4];
    #pragma unroll
    for (int j2 = 0; j2 < 4; j2++) {
        uint32_t row = (uint32_t)(warp_n * 64 + j2 * 16 + brow16);
        ldsm_x4(b[0][j2], bufB + row * 128 + (((uint32_t)(bkh * 16)) ^ ((row & 7) << 4)));
    }
    #pragma unroll
    for (int ks = 0; ks < 4; ks++) {
        if (ks < 3) {                        // prefetch next ks B frags
            #pragma unroll
            for (int j2 = 0; j2 < 4; j2++) {
                uint32_t row = (uint32_t)(warp_n * 64 + j2 * 16 + brow16);
                ldsm_x4(b[(ks + 1) & 1][j2], bufB + row * 128 +
                        (((uint32_t)((ks + 1) * 32 + bkh * 16)) ^ ((row & 7) << 4)));
            }
        }
        uint32_t a[4][4];
        #pragma unroll
        for (int i = 0; i < 4; i++)
            ldsm_x4(a[i], bufA + (aRowBase + 16 * i) * 128 + (((uint32_t)(ks * 32 + lh * 16)) ^ aXr));
        #pragma unroll
        for (int i = 0; i < 4; i++)
            #pragma unroll
            for (int j2 = 0; j2 < 4; j2++) {
                mma_bf16(acc[i][j2 * 2],     a[i], &b[ks & 1][j2][0]);
                mma_bf16(acc[i][j2 * 2 + 1], a[i], &b[ks & 1][j2][2]);
            }
    }
}

// ---------------------------------------------------------------- main fused kernel
__global__ void __launch_bounds__(256, 1)
router_main(const float* __restrict__ gamma, const float* __restrict__ beta,
            const float* __restrict__ b1,    const float* __restrict__ b2,
            const float* __restrict__ cent) {
    extern __shared__ char smem[];
    const uint32_t sb = smem_u32(smem);
    const int tid = threadIdx.x;
    const int wid = tid >> 5;
    const int lane = tid & 31;
    const int warp_m = wid >> 2;
    const int warp_n = wid & 3;
    const int t  = blockIdx.y;
    const int bx = blockIdx.x;
    const int b0 = bx * BM;

    const uint4* featv = reinterpret_cast<const uint4*>(g_featb) + (size_t)b0 * 64;
    const uint4* w1v   = reinterpret_cast<const uint4*>(g_W1b) + (size_t)t * HDn * 64;
    const uint4* w2v   = reinterpret_cast<const uint4*>(g_W2b) + (size_t)t * VDP * 32;

    // kick off GEMM1 chunk 0 ASAP (overlaps bias loads)
    stage_rows<4>(sb + SM_SA0, featv, 64, 0, tid);
    stage_rows<8>(sb + SM_SB0, w1v,   64, 0, tid);
    CP_COMMIT();

    float* s_gamma = reinterpret_cast<float*>(smem + SM_GAMMA);
    float* s_beta  = reinterpret_cast<float*>(smem + SM_BETA);
    float* s_b1    = reinterpret_cast<float*>(smem + SM_B1);
    float* s_b2    = reinterpret_cast<float*>(smem + SM_B2);
    float* s_cent  = reinterpret_cast<float*>(smem + SM_CENT);
    for (int i = tid; i < HDn; i += 256) {
        s_gamma[i] = gamma[t * HDn + i];
        s_beta[i]  = beta[t * HDn + i];
        s_b1[i]    = b1[t * HDn + i];
    }
    for (int i = tid; i < VDn; i += 256) {
        s_b2[i]   = b2[t * VDn + i];
        s_cent[i] = cent[t * VDn + i];
    }

    float acc[4][8][4];
    #pragma unroll
    for (int i = 0; i < 4; i++)
        #pragma unroll
        for (int j = 0; j < 8; j++)
            #pragma unroll
            for (int k = 0; k < 4; k++) acc[i][j][k] = 0.f;

    // ================= GEMM1: h[128x256] = A[128x512] . W1[t]^T, K in 8 chunks of 64
    // one sync per chunk: wait(k) -> sync -> stage(k+1) -> compute(k)
    for (int kc = 0; kc < 8; kc++) {
        CP_WAIT0();
        __syncthreads();           // all warps finished compute(kc-1); buffer (kc+1)&1 free
        if (kc < 7) {
            const uint32_t nb = (kc + 1) & 1;
            stage_rows<4>(sb + (nb ? SM_SA1 : SM_SA0), featv, 64, (kc + 1) * 8, tid);
            stage_rows<8>(sb + (nb ? SM_SB1 : SM_SB0), w1v,   64, (kc + 1) * 8, tid);
        } else {
            // prefetch GEMM2 chunk 0 (W2 pass 0, K chunk 0) into SB0
            stage_rows<8>(sb + SM_SB0, w2v, 32, 0, tid);
        }
        CP_COMMIT();
        compute_chunk(sb + ((kc & 1) ? SM_SA1 : SM_SA0),
                      sb + ((kc & 1) ? SM_SB1 : SM_SB0),
                      acc, warp_m, warp_n, lane);
    }
    __syncthreads();               // all compute done before h-store readers below

    // store h (+b1) as bf16 into swizzled s_h chunks
    #pragma unroll
    for (int i = 0; i < 4; i++) {
        int row0 = warp_m * 64 + i * 16 + (lane >> 2);
        #pragma unroll
        for (int rr = 0; rr < 2; rr++) {
            int row = row0 + rr * 8;
            uint32_t xr = (uint32_t)((row & 7) << 4);
            #pragma unroll
            for (int j = 0; j < 8; j++) {
                int col = warp_n * 64 + j * 8 + (lane & 3) * 2;
                float v0 = acc[i][j][rr * 2 + 0] + s_b1[col];
                float v1 = acc[i][j][rr * 2 + 1] + s_b1[col + 1];
                __nv_bfloat162 pk = __floats2bfloat162_rn(v0, v1);
                uint32_t addr = sb + SM_H + (uint32_t)(col >> 6) * 16384 +
                                (uint32_t)row * 128 + ((uint32_t)((col & 63) * 2) ^ xr);
                asm volatile("st.shared.b32 [%0], %1;" :: "r"(addr), "r"(*(uint32_t*)&pk) : "memory");
            }
        }
    }
    __syncthreads();

    // ================= LayerNorm + exact GELU, in place on s_h
    {
        const int row = tid >> 1, hf = tid & 1;
        const uint32_t xr = (uint32_t)((row & 7) << 4);
        uint32_t hv[64];
        float sum = 0.f, sq = 0.f;
        #pragma unroll
        for (int ch = 0; ch < 2; ch++) {
            uint32_t cb = sb + SM_H + (uint32_t)(2 * hf + ch) * 16384 + (uint32_t)row * 128;
            #pragma unroll
            for (int q = 0; q < 32; q++) {
                uint32_t v;
                asm volatile("ld.shared.b32 %0, [%1];" : "=r"(v) : "r"(cb + (((uint32_t)(q * 4)) ^ xr)));
                hv[ch * 32 + q] = v;
                float2 f = __bfloat1622float2(*reinterpret_cast<__nv_bfloat162*>(&v));
                sum += f.x + f.y; sq += f.x * f.x + f.y * f.y;
            }
        }
        sum += __shfl_xor_sync(0xffffffffu, sum, 1);
        sq  += __shfl_xor_sync(0xffffffffu, sq, 1);
        const float mu = sum * (1.0f / HDn);
        const float var = sq * (1.0f / HDn) - mu * mu;
        const float rs = rsqrtf(var + 1e-5f);
        #pragma unroll
        for (int ch = 0; ch < 2; ch++) {
            uint32_t cb = sb + SM_H + (uint32_t)(2 * hf + ch) * 16384 + (uint32_t)row * 128;
            #pragma unroll
            for (int q = 0; q < 32; q++) {
                int col = hf * 128 + ch * 64 + q * 2;
                uint32_t v = hv[ch * 32 + q];
                float2 f = __bfloat1622float2(*reinterpret_cast<__nv_bfloat162*>(&v));
                float x0 = (f.x - mu) * rs * s_gamma[col]     + s_beta[col];
                float x1 = (f.y - mu) * rs * s_gamma[col + 1] + s_beta[col + 1];
                __nv_bfloat162 pk = __floats2bfloat162_rn(gelu_exact(x0), gelu_exact(x1));
                asm volatile("st.shared.b32 [%0], %1;"
                    :: "r"(cb + (((uint32_t)(q * 4)) ^ xr)), "r"(*(uint32_t*)&pk) : "memory");
            }
        }
    }

    // ================= GEMM2: v[128x512pad] = h[128x256] . W2[t]^T
    // 8 continuous chunks: pass = c>>2 (N 256 halves), kc = c&3 (K chunks of 64)
    float dotp[8], nvp[8];
    #pragma unroll
    for (int k = 0; k < 8; k++) { dotp[k] = 0.f; nvp[k] = 0.f; }
    #pragma unroll
    for (int i = 0; i < 4; i++)
        #pragma unroll
        for (int j = 0; j < 8; j++)
            #pragma unroll
            for (int k = 0; k < 4; k++) acc[i][j][k] = 0.f;

    for (int c = 0; c < 8; c++) {
        CP_WAIT0();
        __syncthreads();           // LN writers done (c=0) / compute(c-1) done; buffer free
        if (c < 7) {
            int cn = c + 1;
            stage_rows<8>(sb + ((cn & 1) ? SM_SB1 : SM_SB0),
                          w2v + (size_t)((cn >> 2) * 256) * 32, 32, (cn & 3) * 8, tid);
            CP_COMMIT();
        }
        compute_chunk(sb + SM_H + (uint32_t)(c & 3) * 16384,
                      sb + ((c & 1) ? SM_SB1 : SM_SB0),
                      acc, warp_m, warp_n, lane);

        if ((c & 3) == 3) {
            const int p = c >> 2;
            // cosine partials (register-resident, deterministic per-thread ownership)
            #pragma unroll
            for (int i = 0; i < 4; i++) {
                #pragma unroll
                for (int rr = 0; rr < 2; rr++) {
                    int lr = i * 2 + rr;
                    #pragma unroll
                    for (int j = 0; j < 8; j++) {
                        int col = p * 256 + warp_n * 64 + j * 8 + (lane & 3) * 2;
                        #pragma unroll
                        for (int cc = 0; cc < 2; cc++) {
                            int cidx = col + cc;
                            if (cidx < VDn) {
                                float v = acc[i][j][rr * 2 + cc] + s_b2[cidx];
                                dotp[lr] += v * s_cent[cidx];
                                nvp[lr]  += v * v;
                            }
                            acc[i][j][rr * 2 + cc] = 0.f;   // reset for next pass
                        }
                    }
                }
            }
        }
    }
    __syncthreads();               // all reads of SA0 region done before overlay write

    // ================= deterministic reduction
    {
        float* s_dot = reinterpret_cast<float*>(smem + SM_DOT);
        float* s_nv  = reinterpret_cast<float*>(smem + SM_NV);
        int slot = warp_n * 4 + (lane & 3);
        #pragma unroll
        for (int i = 0; i < 4; i++)
            #pragma unroll
            for (int rr = 0; rr < 2; rr++) {
                int row = warp_m * 64 + i * 16 + (lane >> 2) + rr * 8;
                s_dot[row * 16 + slot] = dotp[i * 2 + rr];
                s_nv [row * 16 + slot] = nvp [i * 2 + rr];
            }
        __syncthreads();
        float contrib = 0.f;
        if (tid < 128) {
            float dt = 0.f, nv = 0.f;
            #pragma unroll
            for (int s = 0; s < 16; s++) { dt += s_dot[tid * 16 + s]; nv += s_nv[tid * 16 + s]; }
            float vn = fmaxf(sqrtf(nv), 1e-8f);
            contrib = 1.0f - dt / (vn * g_cnorm[t]);
        }
        for (int o = 16; o; o >>= 1) contrib += __shfl_down_sync(0xffffffffu, contrib, o);
        float* red8 = reinterpret_cast<float*>(smem + SM_RED8);
        if (lane == 0) red8[wid] = contrib;
        __syncthreads();
        if (tid == 0)
            g_part[t * 32 + bx] = red8[0] + red8[1] + red8[2] + red8[3];  // warps 4-7 hold 0
    }
}

// ---------------------------------------------------------------- finalize: mean + argmin
__global__ void finalize_kernel(float* __restrict__ out, int out_size) {
    __shared__ float d[Tn];
    int t = threadIdx.x;
    if (t < Tn) {
        float s = 0.f;
        for (int b = 0; b < 32; b++) s += g_part[t * 32 + b];   // fixed order: deterministic
        float dist = s * (1.0f / Bn);
        d[t] = dist;
        if (out_size >= Tn) out[t] = dist;
    }
    __syncthreads();
    if (t == 0) {
        int best = 0; float bv = d[0];
        for (int i = 1; i < Tn; i++) if (d[i] < bv) { bv = d[i]; best = i; }
        if (out_size > Tn)       out[Tn] = (float)best;
        else if (out_size == 1)  reinterpret_cast<int*>(out)[0] = best;
    }
}

// ---------------------------------------------------------------- launch
extern "C" void kernel_launch(void* const* d_in, const int* in_sizes, int n_in,
                              void* d_out, int out_size) {
    const float* t_feat = (const float*)d_in[0];
    const float* W1     = (const float*)d_in[1];
    const float* b1     = (const float*)d_in[2];
    const float* gamma  = (const float*)d_in[3];
    const float* beta   = (const float*)d_in[4];
    const float* W2     = (const float*)d_in[5];
    const float* b2     = (const float*)d_in[6];
    const float* cent   = (const float*)d_in[7];

    cudaFuncSetAttribute(router_main, cudaFuncAttributeMaxDynamicSharedMemorySize, SMEM_TOTAL);

    prep_kernel<<<PREP_BLOCKS, 256>>>(W1, t_feat, W2, cent);

    dim3 grid(32, Tn);
    router_main<<<grid, 256, SMEM_TOTAL>>>(gamma, beta, b1, b2, cent);

    finalize_kernel<<<1, Tn>>>((float*)d_out, out_size);
}